// round 7
// baseline (speedup 1.0000x reference)
#include <cuda_runtime.h>
#include <cstdint>

#define T_TOK   8192
#define HID     1024
#define FFN_DIM 4096
#define NEXP    8
#define TOTAL   (2 * T_TOK)

#define BM 128
#define BN 128
#define BK 16
#define NTHREADS 256

typedef unsigned long long u64t;

__device__ int   g_counts[NEXP];
__device__ int   g_offsets[NEXP];
__device__ int   g_writePos[NEXP];
__device__ int   g_top2[T_TOK * 2];
__device__ int   g_entries[TOTAL];
__device__ float g_h1[(size_t)TOTAL * FFN_DIM];
__device__ float g_partial[2][T_TOK][HID];

__device__ __forceinline__ void unpack2(u64t v, float& lo, float& hi) {
    asm("mov.b64 {%0, %1}, %2;" : "=f"(lo), "=f"(hi) : "l"(v));
}
__device__ __forceinline__ void fma2(u64t& c, u64t a, u64t b) {
    asm("fma.rn.f32x2 %0, %1, %2, %0;" : "+l"(c) : "l"(a), "l"(b));
}

// ---------------- routing ----------------
__global__ void zero_counts_kernel() {
    if (threadIdx.x < NEXP) g_counts[threadIdx.x] = 0;
}

__global__ void gate_kernel(const float* __restrict__ x,
                            const float* __restrict__ gate_w,
                            const float* __restrict__ gate_b) {
    int warp = (blockIdx.x * blockDim.x + threadIdx.x) >> 5;
    int lane = threadIdx.x & 31;
    if (warp >= T_TOK) return;
    const float* xr = x + (size_t)warp * HID;
    float acc[NEXP];
#pragma unroll
    for (int e = 0; e < NEXP; e++) acc[e] = 0.f;
    for (int h = lane; h < HID; h += 32) {
        float xv = xr[h];
#pragma unroll
        for (int e = 0; e < NEXP; e++) acc[e] += xv * gate_w[h * NEXP + e];
    }
#pragma unroll
    for (int e = 0; e < NEXP; e++)
#pragma unroll
        for (int o = 16; o > 0; o >>= 1)
            acc[e] += __shfl_down_sync(0xffffffffu, acc[e], o);
    if (lane == 0) {
        float v1 = -3.4e38f, v2 = -3.4e38f;
        int i1 = 0, i2 = 0;
#pragma unroll
        for (int e = 0; e < NEXP; e++) {
            float v = acc[e] + gate_b[e];
            if (v > v1) { v2 = v1; i2 = i1; v1 = v; i1 = e; }
            else if (v > v2) { v2 = v; i2 = e; }
        }
        g_top2[warp * 2 + 0] = i1;
        g_top2[warp * 2 + 1] = i2;
        atomicAdd(&g_counts[i1], 1);
        atomicAdd(&g_counts[i2], 1);
    }
}

__global__ void scan_kernel() {
    if (threadIdx.x == 0) {
        int off = 0;
        for (int e = 0; e < NEXP; e++) {
            g_offsets[e] = off; g_writePos[e] = off; off += g_counts[e];
        }
    }
}

__global__ void fill_kernel() {
    int t = blockIdx.x * blockDim.x + threadIdx.x;
    if (t >= T_TOK) return;
    int p0 = atomicAdd(&g_writePos[g_top2[t * 2 + 0]], 1);
    g_entries[p0] = t * 2;
    int p1 = atomicAdd(&g_writePos[g_top2[t * 2 + 1]], 1);
    g_entries[p1] = t * 2 + 1;
}

// ---------------- grouped GEMM (f32x2, conflict-free, pack-free) ----------------
// MODE1: A = gather(x) [K=HID],  B = w1[e] [H][F], out = relu(.+b1) -> g_h1
// MODE2: A = g_h1 [K=FFN],       B = w2[e] [F][H], out = .+b2 -> scattered partial
template<int KDIM, bool MODE1>
__global__ __launch_bounds__(NTHREADS, 2)
void gemm_kernel(const float* __restrict__ Asrc,
                 const float* __restrict__ Bw,
                 const float* __restrict__ bias) {
    const int e  = blockIdx.z;
    const int mt = blockIdx.y;
    const int nt = blockIdx.x;
    const int count = g_counts[e];
    if (mt * BM >= count) return;
    const int base = g_offsets[e];

    __shared__ __align__(16) float As[BK][BM + 4];     // [k][m]
    __shared__ __align__(16) float Bs2[BK][2 * BN];    // duplicated pairs

    const int tid = threadIdx.x;
    const int ty = tid >> 4, tx = tid & 15;
    const int aRow0 = tid >> 2;
    const int aCol  = (tid & 3) << 2;
    const int bRow0 = tid >> 5;
    const int bCol  = (tid & 31) << 2;

    const float* Bmat = Bw + (size_t)e * HID * FFN_DIM;

    // A source selected IN DEVICE CODE (g_h1 must not be passed from host)
    const float* Ag = MODE1 ? Asrc : (const float*)g_h1;

    const float* aPtr[2];
#pragma unroll
    for (int p = 0; p < 2; p++) {
        int gi  = base + mt * BM + aRow0 + p * 64;
        int gci = min(gi, TOTAL - 1);
        if (MODE1) {
            int tok = (g_entries[gci] >> 1) & (T_TOK - 1);
            aPtr[p] = Ag + (size_t)tok * HID + aCol;
        } else {
            aPtr[p] = Ag + (size_t)gci * KDIM + aCol;
        }
    }
    const int NPITCH = MODE1 ? FFN_DIM : HID;
    const float* bPtr = Bmat + (size_t)bRow0 * NPITCH + nt * BN + bCol;

    u64t c2[4][8];
#pragma unroll
    for (int p = 0; p < 4; p++)
#pragma unroll
        for (int j = 0; j < 8; j++) c2[p][j] = 0ull;

    float4 aReg[2], bReg[2];
    const int KT = KDIM / BK;
#pragma unroll
    for (int p = 0; p < 2; p++) aReg[p] = *(const float4*)(aPtr[p]);
#pragma unroll
    for (int p = 0; p < 2; p++) bReg[p] = *(const float4*)(bPtr + (size_t)(p * 8) * NPITCH);

    for (int kt = 0; kt < KT; kt++) {
#pragma unroll
        for (int p = 0; p < 2; p++) {
            int row = aRow0 + p * 64;
            As[aCol + 0][row] = aReg[p].x;
            As[aCol + 1][row] = aReg[p].y;
            As[aCol + 2][row] = aReg[p].z;
            As[aCol + 3][row] = aReg[p].w;
            float4 d0, d1;
            d0.x = bReg[p].x; d0.y = bReg[p].x; d0.z = bReg[p].y; d0.w = bReg[p].y;
            d1.x = bReg[p].z; d1.y = bReg[p].z; d1.z = bReg[p].w; d1.w = bReg[p].w;
            *(float4*)&Bs2[bRow0 + p * 8][2 * bCol]     = d0;
            *(float4*)&Bs2[bRow0 + p * 8][2 * bCol + 4] = d1;
        }
        __syncthreads();
        if (kt + 1 < KT) {
            int koff = (kt + 1) * BK;
#pragma unroll
            for (int p = 0; p < 2; p++) aReg[p] = *(const float4*)(aPtr[p] + koff);
#pragma unroll
            for (int p = 0; p < 2; p++)
                bReg[p] = *(const float4*)(bPtr + (size_t)(koff + p * 8) * NPITCH);
        }
#pragma unroll
        for (int k = 0; k < BK; k++) {
            ulonglong2 aq0 = *(const ulonglong2*)&As[k][ty * 8];
            ulonglong2 aq1 = *(const ulonglong2*)&As[k][ty * 8 + 4];
            u64t a2[4] = {aq0.x, aq0.y, aq1.x, aq1.y};
            ulonglong2 bq0 = *(const ulonglong2*)&Bs2[k][tx * 4];
            ulonglong2 bq1 = *(const ulonglong2*)&Bs2[k][64 + tx * 4];
            ulonglong2 bq2 = *(const ulonglong2*)&Bs2[k][128 + tx * 4];
            ulonglong2 bq3 = *(const ulonglong2*)&Bs2[k][192 + tx * 4];
            u64t bv[8] = {bq0.x, bq0.y, bq1.x, bq1.y, bq2.x, bq2.y, bq3.x, bq3.y};
#pragma unroll
            for (int p = 0; p < 4; p++)
#pragma unroll
                for (int j = 0; j < 8; j++) fma2(c2[p][j], a2[p], bv[j]);
        }
        __syncthreads();
    }

    // epilogue: col(q,r) = q*32 + 2*tx + r ; row = ty*8 + 2p + h
    const float* bp = bias + (size_t)e * NPITCH + nt * BN;
    float2 bfrag[4];
#pragma unroll
    for (int q = 0; q < 4; q++) bfrag[q] = *(const float2*)(bp + q * 32 + 2 * tx);

#pragma unroll
    for (int p = 0; p < 4; p++) {
        float vlo[8], vhi[8];
#pragma unroll
        for (int j = 0; j < 8; j++) unpack2(c2[p][j], vlo[j], vhi[j]);
#pragma unroll
        for (int h = 0; h < 2; h++) {
            const float* v = h ? vhi : vlo;
            int row = ty * 8 + 2 * p + h;
            if (mt * BM + row < count) {
                int gi = base + mt * BM + row;
                float* dst;
                if (MODE1) {
                    dst = g_h1 + (size_t)gi * FFN_DIM + nt * BN;
                } else {
                    int entry = g_entries[gi];
                    dst = &g_partial[entry & 1][entry >> 1][nt * BN];
                }
#pragma unroll
                for (int q = 0; q < 4; q++) {
                    float2 o;
                    o.x = v[q * 2 + 0] + bfrag[q].x;
                    o.y = v[q * 2 + 1] + bfrag[q].y;
                    if (MODE1) { o.x = fmaxf(o.x, 0.f); o.y = fmaxf(o.y, 0.f); }
                    *(float2*)(dst + q * 32 + 2 * tx) = o;
                }
            }
        }
    }
}

// ---------------- combine ----------------
__global__ void combine_kernel(float* __restrict__ out) {
    int i = blockIdx.x * blockDim.x + threadIdx.x;
    const int n4 = T_TOK * HID / 4;
    if (i < n4) {
        const float4* p0 = (const float4*)&g_partial[0][0][0];
        const float4* p1 = (const float4*)&g_partial[1][0][0];
        float4 a = p0[i], b = p1[i], r;
        r.x = a.x + b.x; r.y = a.y + b.y; r.z = a.z + b.z; r.w = a.w + b.w;
        ((float4*)out)[i] = r;
    }
}

// ---------------- launch ----------------
extern "C" void kernel_launch(void* const* d_in, const int* in_sizes, int n_in,
                              void* d_out, int out_size) {
    const float* x      = (const float*)d_in[0];
    const float* gate_w = (const float*)d_in[1];
    const float* gate_b = (const float*)d_in[2];
    const float* w1     = (const float*)d_in[3];
    const float* b1     = (const float*)d_in[4];
    const float* w2     = (const float*)d_in[5];
    const float* b2     = (const float*)d_in[6];
    float* out = (float*)d_out;

    zero_counts_kernel<<<1, 32>>>();
    gate_kernel<<<T_TOK / 8, 256>>>(x, gate_w, gate_b);
    scan_kernel<<<1, 32>>>();
    fill_kernel<<<T_TOK / 256, 256>>>();

    dim3 g1(FFN_DIM / BN, (T_TOK + BM - 1) / BM, NEXP);
    gemm_kernel<HID, true><<<g1, NTHREADS>>>(x, w1, b1);

    dim3 g2(HID / BN, (T_TOK + BM - 1) / BM, NEXP);
    gemm_kernel<FFN_DIM, false><<<g2, NTHREADS>>>(x /*unused in MODE2*/, w2, b2);

    combine_kernel<<<(T_TOK * HID / 4 + 255) / 256, 256>>>(out);
}

// round 9
// speedup vs baseline: 1.3547x; 1.3547x over previous
#include <cuda_runtime.h>
#include <cstdint>

#define T_TOK   8192
#define HID     1024
#define FFN_DIM 4096
#define NEXP    8
#define TOTAL   (2 * T_TOK)

#define BM 128
#define BN 128
#define BK 16
#define NTHREADS 256

typedef unsigned long long u64t;

__device__ int   g_counts[NEXP];
__device__ int   g_offsets[NEXP];
__device__ int   g_writePos[NEXP];
__device__ int   g_top2[T_TOK * 2];
__device__ int   g_entries[TOTAL];
__device__ float g_h1[(size_t)TOTAL * FFN_DIM];
__device__ float g_partial[2][T_TOK][HID];

__device__ __forceinline__ u64t pack2(float a) {
    u64t r;
    asm("mov.b64 %0, {%1, %1};" : "=l"(r) : "f"(a));
    return r;
}
__device__ __forceinline__ void unpack2(u64t v, float& lo, float& hi) {
    asm("mov.b64 {%0, %1}, %2;" : "=f"(lo), "=f"(hi) : "l"(v));
}
__device__ __forceinline__ void fma2(u64t& c, u64t a, u64t b) {
    asm("fma.rn.f32x2 %0, %1, %2, %0;" : "+l"(c) : "l"(a), "l"(b));
}

// ---------------- routing ----------------
__global__ void zero_counts_kernel() {
    if (threadIdx.x < NEXP) g_counts[threadIdx.x] = 0;
}

__global__ void gate_kernel(const float* __restrict__ x,
                            const float* __restrict__ gate_w,
                            const float* __restrict__ gate_b) {
    int warp = (blockIdx.x * blockDim.x + threadIdx.x) >> 5;
    int lane = threadIdx.x & 31;
    if (warp >= T_TOK) return;
    const float* xr = x + (size_t)warp * HID;
    float acc[NEXP];
#pragma unroll
    for (int e = 0; e < NEXP; e++) acc[e] = 0.f;
    for (int h = lane; h < HID; h += 32) {
        float xv = xr[h];
#pragma unroll
        for (int e = 0; e < NEXP; e++) acc[e] += xv * gate_w[h * NEXP + e];
    }
#pragma unroll
    for (int e = 0; e < NEXP; e++)
#pragma unroll
        for (int o = 16; o > 0; o >>= 1)
            acc[e] += __shfl_down_sync(0xffffffffu, acc[e], o);
    if (lane == 0) {
        float v1 = -3.4e38f, v2 = -3.4e38f;
        int i1 = 0, i2 = 0;
#pragma unroll
        for (int e = 0; e < NEXP; e++) {
            float v = acc[e] + gate_b[e];
            if (v > v1) { v2 = v1; i2 = i1; v1 = v; i1 = e; }
            else if (v > v2) { v2 = v; i2 = e; }
        }
        g_top2[warp * 2 + 0] = i1;
        g_top2[warp * 2 + 1] = i2;
        atomicAdd(&g_counts[i1], 1);
        atomicAdd(&g_counts[i2], 1);
    }
}

__global__ void scan_kernel() {
    if (threadIdx.x == 0) {
        int off = 0;
        for (int e = 0; e < NEXP; e++) {
            g_offsets[e] = off; g_writePos[e] = off; off += g_counts[e];
        }
    }
}

__global__ void fill_kernel() {
    int t = blockIdx.x * blockDim.x + threadIdx.x;
    if (t >= T_TOK) return;
    int p0 = atomicAdd(&g_writePos[g_top2[t * 2 + 0]], 1);
    g_entries[p0] = t * 2;
    int p1 = atomicAdd(&g_writePos[g_top2[t * 2 + 1]], 1);
    g_entries[p1] = t * 2 + 1;
}

// ---------------- grouped GEMM: conflict-free quarter-split fragments ----------------
// MODE1: A = gather(x) [K=HID],  B = w1[e] [H][F], out = relu(.+b1) -> g_h1
// MODE2: A = g_h1 [K=FFN],       B = w2[e] [F][H], out = .+b2 -> scattered partial
template<int KDIM, bool MODE1>
__global__ __launch_bounds__(NTHREADS, 2)
void gemm_kernel(const float* __restrict__ Asrc,
                 const float* __restrict__ Bw,
                 const float* __restrict__ bias) {
    const int e  = blockIdx.z;
    const int mt = blockIdx.y;
    const int nt = blockIdx.x;
    const int count = g_counts[e];
    if (mt * BM >= count) return;
    const int base = g_offsets[e];

    __shared__ __align__(16) float As[BK][BM + 4];   // [k][m]
    __shared__ __align__(16) float Bs[BK][BN];       // [k][n]

    const int tid = threadIdx.x;
    const int ty = tid >> 4, tx = tid & 15;
    const int aRow0 = tid >> 2;
    const int aCol  = (tid & 3) << 2;
    const int bRow0 = tid >> 5;
    const int bCol  = (tid & 31) << 2;

    const float* Bmat = Bw + (size_t)e * HID * FFN_DIM;
    const float* Ag = MODE1 ? Asrc : (const float*)g_h1;   // device-side select

    const float* aPtr[2];
#pragma unroll
    for (int p = 0; p < 2; p++) {
        int gi  = base + mt * BM + aRow0 + p * 64;
        int gci = min(gi, TOTAL - 1);
        if (MODE1) {
            int tok = (g_entries[gci] >> 1) & (T_TOK - 1);
            aPtr[p] = Ag + (size_t)tok * HID + aCol;
        } else {
            aPtr[p] = Ag + (size_t)gci * KDIM + aCol;
        }
    }
    const int NPITCH = MODE1 ? FFN_DIM : HID;
    const float* bPtr = Bmat + (size_t)bRow0 * NPITCH + nt * BN + bCol;

    // c2[i][j]: row i in {ty*4+i | i<4} ∪ {64+ty*4+i-4}; col-pair j covers
    // cols {tx*4 + 2j, +1} for j<2 and {64 + tx*4 + 2(j-2), +1} for j>=2
    u64t c2[8][4];
#pragma unroll
    for (int i = 0; i < 8; i++)
#pragma unroll
        for (int j = 0; j < 4; j++) c2[i][j] = 0ull;

    float4 aReg[2], bReg[2];
    const int KT = KDIM / BK;
#pragma unroll
    for (int p = 0; p < 2; p++) aReg[p] = *(const float4*)(aPtr[p]);
#pragma unroll
    for (int p = 0; p < 2; p++) bReg[p] = *(const float4*)(bPtr + (size_t)(p * 8) * NPITCH);

    for (int kt = 0; kt < KT; kt++) {
#pragma unroll
        for (int p = 0; p < 2; p++) {
            int row = aRow0 + p * 64;
            As[aCol + 0][row] = aReg[p].x;
            As[aCol + 1][row] = aReg[p].y;
            As[aCol + 2][row] = aReg[p].z;
            As[aCol + 3][row] = aReg[p].w;
            *(float4*)&Bs[bRow0 + p * 8][bCol] = bReg[p];
        }
        __syncthreads();
        if (kt + 1 < KT) {
            int koff = (kt + 1) * BK;
#pragma unroll
            for (int p = 0; p < 2; p++) aReg[p] = *(const float4*)(aPtr[p] + koff);
#pragma unroll
            for (int p = 0; p < 2; p++)
                bReg[p] = *(const float4*)(bPtr + (size_t)(koff + p * 8) * NPITCH);
        }
#pragma unroll
        for (int k = 0; k < BK; k++) {
            // A: broadcast 16B fragments (phase-uniform address) — conflict-free
            float4 a0 = *(const float4*)&As[k][ty * 4];
            float4 a1 = *(const float4*)&As[k][64 + ty * 4];
            // B: contiguous 16B per lane, 8 lanes/phase = 128B — conflict-free
            ulonglong2 b0 = *(const ulonglong2*)&Bs[k][tx * 4];
            ulonglong2 b1 = *(const ulonglong2*)&Bs[k][64 + tx * 4];
            u64t bv[4] = {b0.x, b0.y, b1.x, b1.y};
            u64t a2[8];
            a2[0] = pack2(a0.x); a2[1] = pack2(a0.y);
            a2[2] = pack2(a0.z); a2[3] = pack2(a0.w);
            a2[4] = pack2(a1.x); a2[5] = pack2(a1.y);
            a2[6] = pack2(a1.z); a2[7] = pack2(a1.w);
#pragma unroll
            for (int i = 0; i < 8; i++)
#pragma unroll
                for (int j = 0; j < 4; j++) fma2(c2[i][j], a2[i], bv[j]);
        }
        __syncthreads();
    }

    // epilogue: cols tx*4..+3 (j=0,1) and 64+tx*4..+3 (j=2,3)
    const float* bp = bias + (size_t)e * NPITCH + nt * BN;
    float4 bias0 = *(const float4*)(bp + tx * 4);
    float4 bias1 = *(const float4*)(bp + 64 + tx * 4);

#pragma unroll
    for (int i = 0; i < 8; i++) {
        int row = (i < 4) ? (ty * 4 + i) : (64 + ty * 4 + i - 4);
        if (mt * BM + row < count) {
            int gi = base + mt * BM + row;
            float* dst;
            if (MODE1) {
                dst = g_h1 + (size_t)gi * FFN_DIM + nt * BN;
            } else {
                int entry = g_entries[gi];
                dst = &g_partial[entry & 1][entry >> 1][nt * BN];
            }
            float4 o0, o1;
            unpack2(c2[i][0], o0.x, o0.y);
            unpack2(c2[i][1], o0.z, o0.w);
            unpack2(c2[i][2], o1.x, o1.y);
            unpack2(c2[i][3], o1.z, o1.w);
            o0.x += bias0.x; o0.y += bias0.y; o0.z += bias0.z; o0.w += bias0.w;
            o1.x += bias1.x; o1.y += bias1.y; o1.z += bias1.z; o1.w += bias1.w;
            if (MODE1) {
                o0.x = fmaxf(o0.x, 0.f); o0.y = fmaxf(o0.y, 0.f);
                o0.z = fmaxf(o0.z, 0.f); o0.w = fmaxf(o0.w, 0.f);
                o1.x = fmaxf(o1.x, 0.f); o1.y = fmaxf(o1.y, 0.f);
                o1.z = fmaxf(o1.z, 0.f); o1.w = fmaxf(o1.w, 0.f);
            }
            *(float4*)(dst + tx * 4)      = o0;
            *(float4*)(dst + 64 + tx * 4) = o1;
        }
    }
}

// ---------------- combine ----------------
__global__ void combine_kernel(float* __restrict__ out) {
    int i = blockIdx.x * blockDim.x + threadIdx.x;
    const int n4 = T_TOK * HID / 4;
    if (i < n4) {
        const float4* p0 = (const float4*)&g_partial[0][0][0];
        const float4* p1 = (const float4*)&g_partial[1][0][0];
        float4 a = p0[i], b = p1[i], r;
        r.x = a.x + b.x; r.y = a.y + b.y; r.z = a.z + b.z; r.w = a.w + b.w;
        ((float4*)out)[i] = r;
    }
}

// ---------------- launch ----------------
extern "C" void kernel_launch(void* const* d_in, const int* in_sizes, int n_in,
                              void* d_out, int out_size) {
    const float* x      = (const float*)d_in[0];
    const float* gate_w = (const float*)d_in[1];
    const float* gate_b = (const float*)d_in[2];
    const float* w1     = (const float*)d_in[3];
    const float* b1     = (const float*)d_in[4];
    const float* w2     = (const float*)d_in[5];
    const float* b2     = (const float*)d_in[6];
    float* out = (float*)d_out;

    zero_counts_kernel<<<1, 32>>>();
    gate_kernel<<<T_TOK / 8, 256>>>(x, gate_w, gate_b);
    scan_kernel<<<1, 32>>>();
    fill_kernel<<<T_TOK / 256, 256>>>();

    dim3 g1(FFN_DIM / BN, (T_TOK + BM - 1) / BM, NEXP);
    gemm_kernel<HID, true><<<g1, NTHREADS>>>(x, w1, b1);

    dim3 g2(HID / BN, (T_TOK + BM - 1) / BM, NEXP);
    gemm_kernel<FFN_DIM, false><<<g2, NTHREADS>>>(x /*unused in MODE2*/, w2, b2);

    combine_kernel<<<(T_TOK * HID / 4 + 255) / 256, 256>>>(out);
}